// round 4
// baseline (speedup 1.0000x reference)
#include <cuda_runtime.h>
#include <math.h>

#define BB 4
#define NN 10000
#define EE 160000
#define CC 128
#define ITERS 3
#define M_TOTAL (BB * NN)          // 40000 rows, = 625 * 64 exactly
#define TM 64
#define GEMM_THREADS 256
#define GEMM_SMEM_BYTES ((TM * CC + CC * CC) * 4)   // 96 KB

// ---------------- scratch (static device globals; no runtime allocation) ----
__device__ __align__(16) float g_EA [M_TOTAL * CC];   // exp(states@Wsa + att_b)
__device__ __align__(16) float g_EL [M_TOTAL * CC];   // exp(states@Wla)
__device__ __align__(16) float g_ELS[M_TOTAL * CC];   // EL * states
__device__ __align__(16) float g_G  [M_TOTAL * CC];   // linked_gated
__device__ __align__(16) float g_SS [M_TOTAL * CC];   // states / norm
__device__ int g_deg[M_TOTAL];
__device__ int g_cur[M_TOTAL];
__device__ int g_off[BB * (NN + 1)];
__device__ int g_adj[BB * 2 * EE];

// ---------------- CSR build ------------------------------------------------
__global__ void zero_deg_kernel() {
    int i = blockIdx.x * blockDim.x + threadIdx.x;
    if (i < M_TOTAL) g_deg[i] = 0;
}

__global__ void count_kernel(const int* __restrict__ conn) {
    int idx = blockIdx.x * blockDim.x + threadIdx.x;
    if (idx >= BB * EE) return;
    int b = idx / EE;
    int2 uv = ((const int2*)conn)[idx];
    atomicAdd(&g_deg[b * NN + uv.x], 1);
    atomicAdd(&g_deg[b * NN + uv.y], 1);
}

// one block (1024 threads) per batch: exclusive scan of degrees -> offsets
__global__ void scan_kernel() {
    const int CH = 10;                       // 1024*10 >= 10000
    int b = blockIdx.x;
    int t = threadIdx.x;
    int base = t * CH;
    int pref[CH];
    int s = 0;
#pragma unroll
    for (int i = 0; i < CH; i++) {
        int idx = base + i;
        int v = (idx < NN) ? g_deg[b * NN + idx] : 0;
        pref[i] = s;
        s += v;
    }
    int lane = t & 31, wid = t >> 5;
    int inc = s;
#pragma unroll
    for (int o = 1; o < 32; o <<= 1) {
        int n = __shfl_up_sync(0xffffffffu, inc, o);
        if (lane >= o) inc += n;
    }
    __shared__ int wtot[32];
    if (lane == 31) wtot[wid] = inc;
    __syncthreads();
    if (wid == 0) {
        int v = wtot[lane];
        int iv = v;
#pragma unroll
        for (int o = 1; o < 32; o <<= 1) {
            int n = __shfl_up_sync(0xffffffffu, iv, o);
            if (lane >= o) iv += n;
        }
        wtot[lane] = iv - v;                  // warp-exclusive offset
    }
    __syncthreads();
    int texcl = wtot[wid] + (inc - s);        // thread-exclusive offset
#pragma unroll
    for (int i = 0; i < CH; i++) {
        int idx = base + i;
        if (idx < NN) {
            int o = texcl + pref[i];
            g_off[b * (NN + 1) + idx] = o;
            g_cur[b * NN + idx] = o;
        }
    }
    if (t == blockDim.x - 1) g_off[b * (NN + 1) + NN] = texcl + s;
}

__global__ void fill_kernel(const int* __restrict__ conn) {
    int idx = blockIdx.x * blockDim.x + threadIdx.x;
    if (idx >= BB * EE) return;
    int b = idx / EE;
    int2 uv = ((const int2*)conn)[idx];
    int p = atomicAdd(&g_cur[b * NN + uv.x], 1);
    g_adj[b * 2 * EE + p] = uv.y;
    int q = atomicAdd(&g_cur[b * NN + uv.y], 1);
    g_adj[b * 2 * EE + q] = uv.x;
}

// ---------------- GEMM [40000,128] x [128,128] with fused epilogues --------
// MODE 0: O1 = tanh(acc + bias)                       (init states; X=objects)
// MODE 1: O1 = exp(acc + bias)                        (EA)
// MODE 2: O1 = exp(acc) (EL);  O2 = EL * X[row][c]    (ELS; X=states)
// MODE 3: O1 = tanh(acc + add[row][c] + bias)         (state update; X=G, add=SS)
template <int MODE>
__global__ void gemm_k(const float* __restrict__ X, const float* __restrict__ W,
                       const float* __restrict__ bias, const float* __restrict__ add,
                       float* __restrict__ O1, float* __restrict__ O2) {
    extern __shared__ float sm[];
    float* Xs = sm;               // TM x CC
    float* Ws = sm + TM * CC;     // CC x CC
    int t = threadIdx.x;
    int block_row = blockIdx.x * TM;

    const float4* W4 = (const float4*)W;
    float4* Ws4 = (float4*)Ws;
#pragma unroll
    for (int i = 0; i < 16; i++) Ws4[t + 256 * i] = W4[t + 256 * i];

    const float4* X4 = (const float4*)(X + (size_t)block_row * CC);
    float4* Xs4 = (float4*)Xs;
#pragma unroll
    for (int i = 0; i < 8; i++) Xs4[t + 256 * i] = X4[t + 256 * i];
    __syncthreads();

    int tx = t & 31, ty = t >> 5;           // tx: col group, ty: row group
    float acc[8][4];
#pragma unroll
    for (int r = 0; r < 8; r++) {
        acc[r][0] = 0.f; acc[r][1] = 0.f; acc[r][2] = 0.f; acc[r][3] = 0.f;
    }

#pragma unroll 8
    for (int k = 0; k < CC; k++) {
        float4 w = *(const float4*)&Ws[k * CC + tx * 4];
#pragma unroll
        for (int r = 0; r < 8; r++) {
            float x = Xs[(ty * 8 + r) * CC + k];
            acc[r][0] = fmaf(x, w.x, acc[r][0]);
            acc[r][1] = fmaf(x, w.y, acc[r][1]);
            acc[r][2] = fmaf(x, w.z, acc[r][2]);
            acc[r][3] = fmaf(x, w.w, acc[r][3]);
        }
    }

    int c0 = tx * 4;
    float4 bz = make_float4(0.f, 0.f, 0.f, 0.f);
    if (MODE == 0 || MODE == 1 || MODE == 3) bz = *(const float4*)&bias[c0];

#pragma unroll
    for (int r = 0; r < 8; r++) {
        size_t grow = (size_t)(block_row + ty * 8 + r);
        if (MODE == 0) {
            float4 o;
            o.x = tanhf(acc[r][0] + bz.x);
            o.y = tanhf(acc[r][1] + bz.y);
            o.z = tanhf(acc[r][2] + bz.z);
            o.w = tanhf(acc[r][3] + bz.w);
            *(float4*)&O1[grow * CC + c0] = o;
        } else if (MODE == 1) {
            float4 o;
            o.x = __expf(acc[r][0] + bz.x);
            o.y = __expf(acc[r][1] + bz.y);
            o.z = __expf(acc[r][2] + bz.z);
            o.w = __expf(acc[r][3] + bz.w);
            *(float4*)&O1[grow * CC + c0] = o;
        } else if (MODE == 2) {
            float4 el;
            el.x = __expf(acc[r][0]);
            el.y = __expf(acc[r][1]);
            el.z = __expf(acc[r][2]);
            el.w = __expf(acc[r][3]);
            float4 st = *(const float4*)&Xs[(ty * 8 + r) * CC + c0];
            float4 els;
            els.x = el.x * st.x; els.y = el.y * st.y;
            els.z = el.z * st.z; els.w = el.w * st.w;
            *(float4*)&O1[grow * CC + c0] = el;
            *(float4*)&O2[grow * CC + c0] = els;
        } else {  // MODE 3
            float4 ad = *(const float4*)&add[grow * CC + c0];
            float4 o;
            o.x = tanhf(acc[r][0] + ad.x + bz.x);
            o.y = tanhf(acc[r][1] + ad.y + bz.y);
            o.z = tanhf(acc[r][2] + ad.z + bz.z);
            o.w = tanhf(acc[r][3] + ad.w + bz.w);
            *(float4*)&O1[grow * CC + c0] = o;
        }
    }
}

// ---------------- per-node aggregation (one warp per node, no atomics) -----
__global__ void agg_kernel(const float* __restrict__ states) {
    int gw = (blockIdx.x * blockDim.x + threadIdx.x) >> 5;
    int lane = threadIdx.x & 31;
    if (gw >= M_TOTAL) return;
    int b = gw / NN;
    int i = gw - b * NN;

    int e  = g_off[b * (NN + 1) + i];
    int e2 = g_off[b * (NN + 1) + i + 1];
    const int* __restrict__ adj = g_adj + (size_t)b * 2 * EE;
    const float4* __restrict__ EL4  = (const float4*)(g_EL  + (size_t)b * NN * CC);
    const float4* __restrict__ ELS4 = (const float4*)(g_ELS + (size_t)b * NN * CC);

    float4 sE = make_float4(0.f, 0.f, 0.f, 0.f);
    float4 sS = make_float4(0.f, 0.f, 0.f, 0.f);

    for (; e + 4 <= e2; e += 4) {
        int j0 = __ldg(adj + e);
        int j1 = __ldg(adj + e + 1);
        int j2 = __ldg(adj + e + 2);
        int j3 = __ldg(adj + e + 3);
        float4 a0 = EL4[j0 * 32 + lane];
        float4 a1 = EL4[j1 * 32 + lane];
        float4 a2 = EL4[j2 * 32 + lane];
        float4 a3 = EL4[j3 * 32 + lane];
        float4 c0 = ELS4[j0 * 32 + lane];
        float4 c1 = ELS4[j1 * 32 + lane];
        float4 c2 = ELS4[j2 * 32 + lane];
        float4 c3 = ELS4[j3 * 32 + lane];
        sE.x += a0.x + a1.x + a2.x + a3.x;
        sE.y += a0.y + a1.y + a2.y + a3.y;
        sE.z += a0.z + a1.z + a2.z + a3.z;
        sE.w += a0.w + a1.w + a2.w + a3.w;
        sS.x += c0.x + c1.x + c2.x + c3.x;
        sS.y += c0.y + c1.y + c2.y + c3.y;
        sS.z += c0.z + c1.z + c2.z + c3.z;
        sS.w += c0.w + c1.w + c2.w + c3.w;
    }
    for (; e < e2; e++) {
        int j = __ldg(adj + e);
        float4 a = EL4[j * 32 + lane];
        float4 c = ELS4[j * 32 + lane];
        sE.x += a.x; sE.y += a.y; sE.z += a.z; sE.w += a.w;
        sS.x += c.x; sS.y += c.y; sS.z += c.z; sS.w += c.w;
    }

    size_t row = (size_t)gw * 32 + lane;     // float4 index into [M_TOTAL, CC]
    float4 ea = ((const float4*)g_EA)[row];
    float4 st = ((const float4*)states)[row];
    float4 inv;
    inv.x = 1.f / (1.f + ea.x * sE.x);
    inv.y = 1.f / (1.f + ea.y * sE.y);
    inv.z = 1.f / (1.f + ea.z * sE.z);
    inv.w = 1.f / (1.f + ea.w * sE.w);
    float4 G, SS;
    G.x = ea.x * sS.x * inv.x;  G.y = ea.y * sS.y * inv.y;
    G.z = ea.z * sS.z * inv.z;  G.w = ea.w * sS.w * inv.w;
    SS.x = st.x * inv.x;  SS.y = st.y * inv.y;
    SS.z = st.z * inv.z;  SS.w = st.w * inv.w;
    ((float4*)g_G)[row]  = G;
    ((float4*)g_SS)[row] = SS;
}

// ---------------- launch ----------------------------------------------------
extern "C" void kernel_launch(void* const* d_in, const int* in_sizes, int n_in,
                              void* d_out, int out_size) {
    const float* objects = (const float*)d_in[0];
    const float* Wos     = (const float*)d_in[1];
    const float* Wsa     = (const float*)d_in[2];
    const float* Wla     = (const float*)d_in[3];
    const float* att_b   = (const float*)d_in[4];
    const float* Wl      = (const float*)d_in[5];
    const float* st_b    = (const float*)d_in[6];
    const int*   conn    = (const int*)d_in[7];
    float* states = (float*)d_out;            // live states buffer, [B,N,C]

    cudaFuncSetAttribute(gemm_k<0>, cudaFuncAttributeMaxDynamicSharedMemorySize, GEMM_SMEM_BYTES);
    cudaFuncSetAttribute(gemm_k<1>, cudaFuncAttributeMaxDynamicSharedMemorySize, GEMM_SMEM_BYTES);
    cudaFuncSetAttribute(gemm_k<2>, cudaFuncAttributeMaxDynamicSharedMemorySize, GEMM_SMEM_BYTES);
    cudaFuncSetAttribute(gemm_k<3>, cudaFuncAttributeMaxDynamicSharedMemorySize, GEMM_SMEM_BYTES);

    float *pEA, *pEL, *pELS, *pG, *pSS;
    cudaGetSymbolAddress((void**)&pEA,  g_EA);
    cudaGetSymbolAddress((void**)&pEL,  g_EL);
    cudaGetSymbolAddress((void**)&pELS, g_ELS);
    cudaGetSymbolAddress((void**)&pG,   g_G);
    cudaGetSymbolAddress((void**)&pSS,  g_SS);

    const int EDGE_BLOCKS = (BB * EE + 255) / 256;      // 2500
    const int GEMM_GRID   = M_TOTAL / TM;               // 625
    const int AGG_GRID    = (M_TOTAL * 32 + 255) / 256; // 5000

    // CSR build (per launch; connections are an input)
    zero_deg_kernel<<<(M_TOTAL + 255) / 256, 256>>>();
    count_kernel<<<EDGE_BLOCKS, 256>>>(conn);
    scan_kernel<<<BB, 1024>>>();
    fill_kernel<<<EDGE_BLOCKS, 256>>>(conn);

    // init states = tanh(objects @ Wos + st_b)
    gemm_k<0><<<GEMM_GRID, GEMM_THREADS, GEMM_SMEM_BYTES>>>(objects, Wos, st_b, nullptr, states, nullptr);

    for (int it = 0; it < ITERS; it++) {
        gemm_k<1><<<GEMM_GRID, GEMM_THREADS, GEMM_SMEM_BYTES>>>(states, Wsa, att_b, nullptr, pEA, nullptr);
        gemm_k<2><<<GEMM_GRID, GEMM_THREADS, GEMM_SMEM_BYTES>>>(states, Wla, nullptr, nullptr, pEL, pELS);
        agg_kernel<<<AGG_GRID, 256>>>(states);
        gemm_k<3><<<GEMM_GRID, GEMM_THREADS, GEMM_SMEM_BYTES>>>(pG, Wl, st_b, pSS, states, nullptr);
    }
}

// round 6
// speedup vs baseline: 1.1770x; 1.1770x over previous
#include <cuda_runtime.h>
#include <cuda_fp16.h>
#include <math.h>

#define BB 4
#define NN 10000
#define EE 160000
#define CC 128
#define ITERS 3
#define M_TOTAL (BB * NN)          // 40000 rows, = 625 * 64 exactly
#define TM 64
#define GEMM_THREADS 256
#define GEMM_SMEM_BYTES ((TM * CC + CC * CC) * 4)   // 96 KB

// ---------------- scratch (static device globals; no runtime allocation) ----
__device__ __align__(16) float g_EA [M_TOTAL * CC];      // exp(states@Wsa + att_b)
__device__ __align__(16) __half g_T[M_TOTAL * 2 * CC];   // per node: [EL(128) | ELS(128)] fp16
__device__ __align__(16) float g_G  [M_TOTAL * CC];      // linked_gated
__device__ __align__(16) float g_SS [M_TOTAL * CC];      // states / norm
__device__ int g_deg[M_TOTAL];
__device__ int g_cur[M_TOTAL];
__device__ int g_off[BB * (NN + 1)];
__device__ int g_adj[BB * 2 * EE];

// ---------------- CSR build ------------------------------------------------
__global__ void zero_deg_kernel() {
    int i = blockIdx.x * blockDim.x + threadIdx.x;
    if (i < M_TOTAL) g_deg[i] = 0;
}

__global__ void count_kernel(const int* __restrict__ conn) {
    int idx = blockIdx.x * blockDim.x + threadIdx.x;
    if (idx >= BB * EE) return;
    int b = idx / EE;
    int2 uv = ((const int2*)conn)[idx];
    atomicAdd(&g_deg[b * NN + uv.x], 1);
    atomicAdd(&g_deg[b * NN + uv.y], 1);
}

// one block (1024 threads) per batch: exclusive scan of degrees -> offsets
__global__ void scan_kernel() {
    const int CH = 10;                       // 1024*10 >= 10000
    int b = blockIdx.x;
    int t = threadIdx.x;
    int base = t * CH;
    int pref[CH];
    int s = 0;
#pragma unroll
    for (int i = 0; i < CH; i++) {
        int idx = base + i;
        int v = (idx < NN) ? g_deg[b * NN + idx] : 0;
        pref[i] = s;
        s += v;
    }
    int lane = t & 31, wid = t >> 5;
    int inc = s;
#pragma unroll
    for (int o = 1; o < 32; o <<= 1) {
        int n = __shfl_up_sync(0xffffffffu, inc, o);
        if (lane >= o) inc += n;
    }
    __shared__ int wtot[32];
    if (lane == 31) wtot[wid] = inc;
    __syncthreads();
    if (wid == 0) {
        int v = wtot[lane];
        int iv = v;
#pragma unroll
        for (int o = 1; o < 32; o <<= 1) {
            int n = __shfl_up_sync(0xffffffffu, iv, o);
            if (lane >= o) iv += n;
        }
        wtot[lane] = iv - v;                  // warp-exclusive offset
    }
    __syncthreads();
    int texcl = wtot[wid] + (inc - s);        // thread-exclusive offset
#pragma unroll
    for (int i = 0; i < CH; i++) {
        int idx = base + i;
        if (idx < NN) {
            int o = texcl + pref[i];
            g_off[b * (NN + 1) + idx] = o;
            g_cur[b * NN + idx] = o;
        }
    }
    if (t == blockDim.x - 1) g_off[b * (NN + 1) + NN] = texcl + s;
}

__global__ void fill_kernel(const int* __restrict__ conn) {
    int idx = blockIdx.x * blockDim.x + threadIdx.x;
    if (idx >= BB * EE) return;
    int b = idx / EE;
    int2 uv = ((const int2*)conn)[idx];
    int p = atomicAdd(&g_cur[b * NN + uv.x], 1);
    g_adj[b * 2 * EE + p] = uv.y;
    int q = atomicAdd(&g_cur[b * NN + uv.y], 1);
    g_adj[b * 2 * EE + q] = uv.x;
}

// ---------------- GEMM [40000,128] x [128,128] with fused epilogues --------
// MODE 0: O1 = tanh(acc + bias)                        (init states; X=objects)
// MODE 1: O1 = exp(acc + bias)                         (EA)
// MODE 2: T[row] = { fp16(exp(acc)), fp16(exp(acc)*X[row][c]) }   (EL|ELS combined)
// MODE 3: O1 = tanh(acc + add[row][c] + bias)          (state update; X=G, add=SS)
template <int MODE>
__global__ void gemm_k(const float* __restrict__ X, const float* __restrict__ W,
                       const float* __restrict__ bias, const float* __restrict__ add,
                       float* __restrict__ O1, __half* __restrict__ OT) {
    extern __shared__ float sm[];
    float* Xs = sm;               // TM x CC
    float* Ws = sm + TM * CC;     // CC x CC
    int t = threadIdx.x;
    int block_row = blockIdx.x * TM;

    const float4* W4 = (const float4*)W;
    float4* Ws4 = (float4*)Ws;
#pragma unroll
    for (int i = 0; i < 16; i++) Ws4[t + 256 * i] = W4[t + 256 * i];

    const float4* X4 = (const float4*)(X + (size_t)block_row * CC);
    float4* Xs4 = (float4*)Xs;
#pragma unroll
    for (int i = 0; i < 8; i++) Xs4[t + 256 * i] = X4[t + 256 * i];
    __syncthreads();

    int tx = t & 31, ty = t >> 5;           // tx: col group, ty: row group
    float acc[8][4];
#pragma unroll
    for (int r = 0; r < 8; r++) {
        acc[r][0] = 0.f; acc[r][1] = 0.f; acc[r][2] = 0.f; acc[r][3] = 0.f;
    }

#pragma unroll 8
    for (int k = 0; k < CC; k++) {
        float4 w = *(const float4*)&Ws[k * CC + tx * 4];
#pragma unroll
        for (int r = 0; r < 8; r++) {
            float x = Xs[(ty * 8 + r) * CC + k];
            acc[r][0] = fmaf(x, w.x, acc[r][0]);
            acc[r][1] = fmaf(x, w.y, acc[r][1]);
            acc[r][2] = fmaf(x, w.z, acc[r][2]);
            acc[r][3] = fmaf(x, w.w, acc[r][3]);
        }
    }

    int c0 = tx * 4;
    float4 bz = make_float4(0.f, 0.f, 0.f, 0.f);
    if (MODE == 0 || MODE == 1 || MODE == 3) bz = *(const float4*)&bias[c0];

#pragma unroll
    for (int r = 0; r < 8; r++) {
        size_t grow = (size_t)(block_row + ty * 8 + r);
        if (MODE == 0) {
            float4 o;
            o.x = tanhf(acc[r][0] + bz.x);
            o.y = tanhf(acc[r][1] + bz.y);
            o.z = tanhf(acc[r][2] + bz.z);
            o.w = tanhf(acc[r][3] + bz.w);
            *(float4*)&O1[grow * CC + c0] = o;
        } else if (MODE == 1) {
            float4 o;
            o.x = __expf(acc[r][0] + bz.x);
            o.y = __expf(acc[r][1] + bz.y);
            o.z = __expf(acc[r][2] + bz.z);
            o.w = __expf(acc[r][3] + bz.w);
            *(float4*)&O1[grow * CC + c0] = o;
        } else if (MODE == 2) {
            float el0 = __expf(acc[r][0]);
            float el1 = __expf(acc[r][1]);
            float el2 = __expf(acc[r][2]);
            float el3 = __expf(acc[r][3]);
            float4 st = *(const float4*)&Xs[(ty * 8 + r) * CC + c0];
            // combined row: [EL(0..127) | ELS(0..127)] fp16
            __half2 e01 = __floats2half2_rn(el0, el1);
            __half2 e23 = __floats2half2_rn(el2, el3);
            __half2 s01 = __floats2half2_rn(el0 * st.x, el1 * st.y);
            __half2 s23 = __floats2half2_rn(el2 * st.z, el3 * st.w);
            uint2 pe, ps;
            pe.x = *(unsigned int*)&e01; pe.y = *(unsigned int*)&e23;
            ps.x = *(unsigned int*)&s01; ps.y = *(unsigned int*)&s23;
            *(uint2*)&OT[grow * 2 * CC + c0]      = pe;
            *(uint2*)&OT[grow * 2 * CC + CC + c0] = ps;
        } else {  // MODE 3
            float4 ad = *(const float4*)&add[grow * CC + c0];
            float4 o;
            o.x = tanhf(acc[r][0] + ad.x + bz.x);
            o.y = tanhf(acc[r][1] + ad.y + bz.y);
            o.z = tanhf(acc[r][2] + ad.z + bz.z);
            o.w = tanhf(acc[r][3] + ad.w + bz.w);
            *(float4*)&O1[grow * CC + c0] = o;
        }
    }
}

// ---------------- per-node aggregation (one warp per node, no atomics) -----
// Combined fp16 table: one LDG.128 per edge per warp fetches EL|ELS (512B).
// Lanes 0-15 accumulate EL channels (8 each), lanes 16-31 accumulate ELS.
__device__ __forceinline__ void acc8_fp16(float* acc, uint4 v) {
    unsigned int u[4] = {v.x, v.y, v.z, v.w};
#pragma unroll
    for (int q = 0; q < 4; q++) {
        float2 f = __half22float2(*(__half2*)&u[q]);
        acc[2 * q]     += f.x;
        acc[2 * q + 1] += f.y;
    }
}

__global__ void agg_kernel(const float* __restrict__ states) {
    int gw = (blockIdx.x * blockDim.x + threadIdx.x) >> 5;
    int lane = threadIdx.x & 31;
    if (gw >= M_TOTAL) return;
    int b = gw / NN;
    int i = gw - b * NN;

    int e  = g_off[b * (NN + 1) + i];
    int e2 = g_off[b * (NN + 1) + i + 1];
    const int* __restrict__ adj = g_adj + (size_t)b * 2 * EE;
    const uint4* __restrict__ T4 = (const uint4*)(g_T + (size_t)b * NN * 2 * CC);

    float acc[8];
#pragma unroll
    for (int k = 0; k < 8; k++) acc[k] = 0.f;

    for (; e + 4 <= e2; e += 4) {
        int j0 = __ldg(adj + e);
        int j1 = __ldg(adj + e + 1);
        int j2 = __ldg(adj + e + 2);
        int j3 = __ldg(adj + e + 3);
        uint4 t0 = T4[(size_t)j0 * 32 + lane];
        uint4 t1 = T4[(size_t)j1 * 32 + lane];
        uint4 t2 = T4[(size_t)j2 * 32 + lane];
        uint4 t3 = T4[(size_t)j3 * 32 + lane];
        acc8_fp16(acc, t0);
        acc8_fp16(acc, t1);
        acc8_fp16(acc, t2);
        acc8_fp16(acc, t3);
    }
    for (; e < e2; e++) {
        int j = __ldg(adj + e);
        uint4 t = T4[(size_t)j * 32 + lane];
        acc8_fp16(acc, t);
    }

    // exchange halves: lanes<16 hold sum(EL), lanes>=16 hold sum(ELS)
    float other[8];
#pragma unroll
    for (int k = 0; k < 8; k++)
        other[k] = __shfl_xor_sync(0xffffffffu, acc[k], 16);

    int sub = lane & 15;                      // channel group: c = sub*8 .. +7
    size_t rowf4 = (size_t)gw * 32 + sub * 2; // float4 index into [M_TOTAL, CC]
    float4 ea0 = ((const float4*)g_EA)[rowf4];
    float4 ea1 = ((const float4*)g_EA)[rowf4 + 1];
    float ea[8] = {ea0.x, ea0.y, ea0.z, ea0.w, ea1.x, ea1.y, ea1.z, ea1.w};

    float sE[8], sS[8];
    if (lane < 16) {
#pragma unroll
        for (int k = 0; k < 8; k++) { sE[k] = acc[k]; sS[k] = other[k]; }
    } else {
#pragma unroll
        for (int k = 0; k < 8; k++) { sE[k] = other[k]; sS[k] = acc[k]; }
    }

    float inv[8];
#pragma unroll
    for (int k = 0; k < 8; k++) inv[k] = 1.f / (1.f + ea[k] * sE[k]);

    if (lane < 16) {
        // write G = ea * sS * inv
        float4 G0, G1;
        G0.x = ea[0] * sS[0] * inv[0]; G0.y = ea[1] * sS[1] * inv[1];
        G0.z = ea[2] * sS[2] * inv[2]; G0.w = ea[3] * sS[3] * inv[3];
        G1.x = ea[4] * sS[4] * inv[4]; G1.y = ea[5] * sS[5] * inv[5];
        G1.z = ea[6] * sS[6] * inv[6]; G1.w = ea[7] * sS[7] * inv[7];
        ((float4*)g_G)[rowf4]     = G0;
        ((float4*)g_G)[rowf4 + 1] = G1;
    } else {
        // write SS = states * inv
        float4 st0 = ((const float4*)states)[rowf4];
        float4 st1 = ((const float4*)states)[rowf4 + 1];
        float4 S0, S1;
        S0.x = st0.x * inv[0]; S0.y = st0.y * inv[1];
        S0.z = st0.z * inv[2]; S0.w = st0.w * inv[3];
        S1.x = st1.x * inv[4]; S1.y = st1.y * inv[5];
        S1.z = st1.z * inv[6]; S1.w = st1.w * inv[7];
        ((float4*)g_SS)[rowf4]     = S0;
        ((float4*)g_SS)[rowf4 + 1] = S1;
    }
}

// ---------------- launch ----------------------------------------------------
extern "C" void kernel_launch(void* const* d_in, const int* in_sizes, int n_in,
                              void* d_out, int out_size) {
    const float* objects = (const float*)d_in[0];
    const float* Wos     = (const float*)d_in[1];
    const float* Wsa     = (const float*)d_in[2];
    const float* Wla     = (const float*)d_in[3];
    const float* att_b   = (const float*)d_in[4];
    const float* Wl      = (const float*)d_in[5];
    const float* st_b    = (const float*)d_in[6];
    const int*   conn    = (const int*)d_in[7];
    float* states = (float*)d_out;            // live states buffer, [B,N,C]

    cudaFuncSetAttribute(gemm_k<0>, cudaFuncAttributeMaxDynamicSharedMemorySize, GEMM_SMEM_BYTES);
    cudaFuncSetAttribute(gemm_k<1>, cudaFuncAttributeMaxDynamicSharedMemorySize, GEMM_SMEM_BYTES);
    cudaFuncSetAttribute(gemm_k<2>, cudaFuncAttributeMaxDynamicSharedMemorySize, GEMM_SMEM_BYTES);
    cudaFuncSetAttribute(gemm_k<3>, cudaFuncAttributeMaxDynamicSharedMemorySize, GEMM_SMEM_BYTES);

    float *pEA, *pG, *pSS;
    __half* pT;
    cudaGetSymbolAddress((void**)&pEA, g_EA);
    cudaGetSymbolAddress((void**)&pT,  g_T);
    cudaGetSymbolAddress((void**)&pG,  g_G);
    cudaGetSymbolAddress((void**)&pSS, g_SS);

    const int EDGE_BLOCKS = (BB * EE + 255) / 256;      // 2500
    const int GEMM_GRID   = M_TOTAL / TM;               // 625
    const int AGG_GRID    = (M_TOTAL * 32 + 255) / 256; // 5000

    // CSR build (per launch; connections are an input)
    zero_deg_kernel<<<(M_TOTAL + 255) / 256, 256>>>();
    count_kernel<<<EDGE_BLOCKS, 256>>>(conn);
    scan_kernel<<<BB, 1024>>>();
    fill_kernel<<<EDGE_BLOCKS, 256>>>(conn);

    // init states = tanh(objects @ Wos + st_b)
    gemm_k<0><<<GEMM_GRID, GEMM_THREADS, GEMM_SMEM_BYTES>>>(objects, Wos, st_b, nullptr, states, nullptr);

    for (int it = 0; it < ITERS; it++) {
        gemm_k<1><<<GEMM_GRID, GEMM_THREADS, GEMM_SMEM_BYTES>>>(states, Wsa, att_b, nullptr, pEA, nullptr);
        gemm_k<2><<<GEMM_GRID, GEMM_THREADS, GEMM_SMEM_BYTES>>>(states, Wla, nullptr, nullptr, nullptr, pT);
        agg_kernel<<<AGG_GRID, 256>>>(states);
        gemm_k<3><<<GEMM_GRID, GEMM_THREADS, GEMM_SMEM_BYTES>>>(pG, Wl, st_b, pSS, states, nullptr);
    }
}